// round 15
// baseline (speedup 1.0000x reference)
#include <cuda_runtime.h>
#include <cuda_fp16.h>
#include <cstdint>

#define BB 4
#define SS 2048
#define DD 1024
#define HH 16
#define HD 64

// Scratch (allocation-free)
__device__ __half g_qh[(size_t)BB * HH * SS * HD];  // q fp16, pre-scaled by 0.125
__device__ __half g_krh[(size_t)BB * HH * SS * HD]; // k fp16 (attention input)
__device__ __half g_vrh[(size_t)BB * HH * SS * HD]; // v fp16 (attention input)
__device__ __half g_a[(size_t)BB * SS * DD];        // attention out (fp16, proj input)
__device__ __half g_xh[(size_t)BB * SS * DD];       // x in fp16
__device__ __half g_wah[(size_t)3 * DD * DD];       // w_attn in fp16
__device__ __half g_wth[(size_t)DD * DD];           // w_proj^T in fp16

// ---------------------------------------------------------------------------
__device__ __forceinline__ uint32_t smem_u32(const void* p) {
    uint32_t a;
    asm("{ .reg .u64 t; cvta.to.shared.u64 t, %1; cvt.u32.u64 %0, t; }"
        : "=r"(a) : "l"(p));
    return a;
}
__device__ __forceinline__ void cp_async16(uint32_t dst, const void* src) {
    asm volatile("cp.async.cg.shared.global [%0], [%1], 16;" :: "r"(dst), "l"(src));
}
#define CP_COMMIT() asm volatile("cp.async.commit_group;" ::: "memory")
#define CP_WAIT(n)  asm volatile("cp.async.wait_group %0;" :: "n"(n) : "memory")

__device__ __forceinline__ void mma_f16(float* c, const uint32_t* a, const uint32_t* b) {
    asm volatile(
        "mma.sync.aligned.m16n8k16.row.col.f32.f16.f16.f32 "
        "{%0,%1,%2,%3}, {%4,%5,%6,%7}, {%8,%9}, {%0,%1,%2,%3};"
        : "+f"(c[0]), "+f"(c[1]), "+f"(c[2]), "+f"(c[3])
        : "r"(a[0]), "r"(a[1]), "r"(a[2]), "r"(a[3]), "r"(b[0]), "r"(b[1]));
}
#define LDSM_X4(r0, r1, r2, r3, addr) \
    asm volatile("ldmatrix.sync.aligned.m8n8.x4.shared.b16 {%0,%1,%2,%3}, [%4];" \
        : "=r"(r0), "=r"(r1), "=r"(r2), "=r"(r3) : "r"(addr))
#define LDSM_X4_T(r0, r1, r2, r3, addr) \
    asm volatile("ldmatrix.sync.aligned.m8n8.x4.trans.shared.b16 {%0,%1,%2,%3}, [%4];" \
        : "=r"(r0), "=r"(r1), "=r"(r2), "=r"(r3) : "r"(addr))

// ---------------------------------------------------------------------------
// Fused prep: w_proj transpose+round (per-block tile) + x / w_attn fp16
// conversion (grid-stride). Grid must be exactly 1024 blocks x 256 threads.
// ---------------------------------------------------------------------------
__global__ __launch_bounds__(256) void prep_kernel(
    const float4* __restrict__ x4, uint2* __restrict__ xh4, int n4x,
    const float4* __restrict__ wa4, uint2* __restrict__ wah4, int n4w,
    const float* __restrict__ wp, __half* __restrict__ wth)
{
    __shared__ float t[32][33];
    const int tid = threadIdx.x;

    // --- w_proj [K,N] -> wth [N,K] (fp16). 1024 blocks = 32x32 tiles.
    {
        const int bx = blockIdx.x & 31;
        const int by = blockIdx.x >> 5;
        const int tx = tid & 31, ty = tid >> 5;
        const int k0 = by * 32, n0 = bx * 32;
#pragma unroll
        for (int i = ty; i < 32; i += 8)
            t[i][tx] = wp[(size_t)(k0 + i) * DD + n0 + tx];
        __syncthreads();
#pragma unroll
        for (int i = ty; i < 32; i += 8)
            wth[(size_t)(n0 + i) * DD + k0 + tx] = __float2half_rn(t[tx][i]);
    }

    // --- x -> fp16
    const int stride = gridDim.x * blockDim.x;
    for (int i = blockIdx.x * 256 + tid; i < n4x; i += stride) {
        float4 v = x4[i];
        __half2 h0 = __floats2half2_rn(v.x, v.y);
        __half2 h1 = __floats2half2_rn(v.z, v.w);
        uint2 o; o.x = *(uint32_t*)&h0; o.y = *(uint32_t*)&h1;
        xh4[i] = o;
    }
    // --- w_attn -> fp16
    for (int i = blockIdx.x * 256 + tid; i < n4w; i += stride) {
        float4 v = wa4[i];
        __half2 h0 = __floats2half2_rn(v.x, v.y);
        __half2 h1 = __floats2half2_rn(v.z, v.w);
        uint2 o; o.x = *(uint32_t*)&h0; o.y = *(uint32_t*)&h1;
        wah4[i] = o;
    }
}

// ---------------------------------------------------------------------------
// fp16 mma.sync GEMM: 128x128 CTA tile, 32x64 warp tile, BK=64 halfs,
// 3-stage cp.async, ldmatrix fragments double-buffered, 2 CTAs/SM.
// MODE 0: C -> out0. MODE 1: q*0.125->g_qh, k->out1+g_krh, v->out2+g_vrh.
// ---------------------------------------------------------------------------
#define KDIM 1024
#define NCHUNK 16
#define STG_BYTES (256 * 144)
#define GEMM_SMEM (3 * STG_BYTES)

template <int MODE>
__global__ __launch_bounds__(256, 2) void mma_gemm_h(
    const __half* __restrict__ A, const __half* __restrict__ Bm,
    const float* __restrict__ bias,
    float* __restrict__ out0, float* __restrict__ out1, float* __restrict__ out2)
{
    extern __shared__ __half smh[];
    const uint32_t sbase = smem_u32(smh);
    const int tid = threadIdx.x;
    const int wid = tid >> 5;
    const int lane = tid & 31;
    const int g = lane >> 2;
    const int tig = lane & 3;
    const int m0 = blockIdx.y * 128;
    const int n0 = blockIdx.x * 128;
    const int wm = (wid & 3) * 32;
    const int wn = (wid >> 2) * 64;

    const uint32_t a_lane = (uint32_t)((((lane >> 3) & 1) * 8 + (lane & 7)) * 144
                                       + ((lane >> 4) & 1) * 16);
    const uint32_t b_lane = (uint32_t)((((lane >> 4) & 1) * 8 + (lane & 7)) * 144
                                       + ((lane >> 3) & 1) * 16);

    float c[2][8][4];
#pragma unroll
    for (int i = 0; i < 2; i++)
#pragma unroll
        for (int j = 0; j < 8; j++)
#pragma unroll
            for (int k = 0; k < 4; k++) c[i][j][k] = 0.f;

    const int lr = tid >> 1;
    const int lcb = (tid & 1) * 64;
    const char* Agc = (const char*)(A + (size_t)(m0 + lr) * KDIM) + lcb;
    const char* Bgc = (const char*)(Bm + (size_t)(n0 + lr) * KDIM) + lcb;

#define ISSUE(chunk) do {                                                           \
    const uint32_t _as = sbase + (uint32_t)((chunk) % 3) * STG_BYTES;               \
    const uint32_t _bs = _as + 128u * 144u;                                         \
    const int _kb = (chunk) * 128;                                                  \
    _Pragma("unroll")                                                               \
    for (int _i = 0; _i < 4; _i++)                                                  \
        cp_async16(_as + (uint32_t)(lr * 144 + lcb + _i * 16), Agc + _kb + _i * 16);\
    _Pragma("unroll")                                                               \
    for (int _i = 0; _i < 4; _i++)                                                  \
        cp_async16(_bs + (uint32_t)(lr * 144 + lcb + _i * 16), Bgc + _kb + _i * 16);\
    CP_COMMIT();                                                                    \
} while (0)

#define LOAD_FRAGS(buf, ks) do {                                                    \
    _Pragma("unroll")                                                               \
    for (int _mt = 0; _mt < 2; _mt++)                                               \
        LDSM_X4(af[buf][_mt][0], af[buf][_mt][1], af[buf][_mt][2], af[buf][_mt][3], \
                aBase + (uint32_t)((wm + _mt * 16) * 144) + a_lane + (ks) * 32);    \
    _Pragma("unroll")                                                               \
    for (int _np = 0; _np < 4; _np++)                                               \
        LDSM_X4(bf[buf][2 * _np][0], bf[buf][2 * _np][1],                           \
                bf[buf][2 * _np + 1][0], bf[buf][2 * _np + 1][1],                   \
                bBase + (uint32_t)((wn + _np * 16) * 144) + b_lane + (ks) * 32);    \
} while (0)

    ISSUE(0);
    ISSUE(1);

    for (int ch = 0; ch < NCHUNK; ch++) {
        if (ch + 1 < NCHUNK) { CP_WAIT(1); } else { CP_WAIT(0); }
        __syncthreads();
        if (ch + 2 < NCHUNK) ISSUE(ch + 2);

        const uint32_t aBase = sbase + (uint32_t)(ch % 3) * STG_BYTES;
        const uint32_t bBase = aBase + 128u * 144u;

        uint32_t af[2][2][4], bf[2][8][2];
        LOAD_FRAGS(0, 0);
#pragma unroll
        for (int ks = 0; ks < 4; ks++) {
            const int cur = ks & 1;
            if (ks < 3) LOAD_FRAGS((ks + 1) & 1, ks + 1);
#pragma unroll
            for (int mt = 0; mt < 2; mt++)
#pragma unroll
                for (int nt = 0; nt < 8; nt++)
                    mma_f16(c[mt][nt], af[cur][mt], bf[cur][nt]);
        }
    }

#pragma unroll
    for (int mt = 0; mt < 2; mt++) {
        const int row0 = m0 + wm + mt * 16 + g;
        const int row1 = row0 + 8;
#pragma unroll
        for (int nt = 0; nt < 8; nt++) {
            const int n = n0 + wn + nt * 8 + 2 * tig;
            const float2 bv = *(const float2*)(bias + n);
            float2 v0, v1;
            v0.x = c[mt][nt][0] + bv.x; v0.y = c[mt][nt][1] + bv.y;
            v1.x = c[mt][nt][2] + bv.x; v1.y = c[mt][nt][3] + bv.y;
            if (MODE == 0) {
                *(float2*)(out0 + (size_t)row0 * DD + n) = v0;
                *(float2*)(out0 + (size_t)row1 * DD + n) = v1;
            } else {
                const int part = n >> 10;
                const int hc = n & (DD - 1);
                const int h = hc >> 6;
                const int d = hc & 63;
                const int b0_ = row0 >> 11, s0_ = row0 & (SS - 1);
                const int b1_ = row1 >> 11, s1_ = row1 & (SS - 1);
                const size_t d0 = (((size_t)(b0_ * HH + h)) * SS + s0_) * HD + d;
                const size_t d1 = (((size_t)(b1_ * HH + h)) * SS + s1_) * HD + d;
                if (part == 0) {
                    *(__half2*)(g_qh + d0) = __floats2half2_rn(v0.x * 0.125f, v0.y * 0.125f);
                    *(__half2*)(g_qh + d1) = __floats2half2_rn(v1.x * 0.125f, v1.y * 0.125f);
                } else if (part == 1) {
                    *(float2*)(out1 + d0) = v0;       // exact -> present
                    *(float2*)(out1 + d1) = v1;
                    *(__half2*)(g_krh + d0) = __floats2half2_rn(v0.x, v0.y);
                    *(__half2*)(g_krh + d1) = __floats2half2_rn(v1.x, v1.y);
                } else {
                    *(float2*)(out2 + d0) = v0;
                    *(float2*)(out2 + d1) = v1;
                    *(__half2*)(g_vrh + d0) = __floats2half2_rn(v0.x, v0.y);
                    *(__half2*)(g_vrh + d1) = __floats2half2_rn(v1.x, v1.y);
                }
            }
        }
    }
}

// ---------------------------------------------------------------------------
// fp16 tensor-core causal flash attention, 256 queries / CTA (512 threads,
// 16 warps), key tiles of 64, 2 stages, 1 CTA/SM (regs), heaviest blocks first.
// ---------------------------------------------------------------------------
#define HKOFF(s) ((uint32_t)(s) * 9216u)
#define HVOFF(s) (18432u + (uint32_t)(s) * 9216u)
#define HPOFF 36864u
#define ATT_SMEM (36864 + 256 * 144)   // 73728

__global__ __launch_bounds__(512, 1) void attn_h(
    const __half* __restrict__ qh, const __half* __restrict__ kh,
    const __half* __restrict__ vh)
{
    extern __shared__ char smc[];
    const uint32_t sb = smem_u32(smc);
    const int tid = threadIdx.x;
    const int w = tid >> 5, lane = tid & 31;
    const int g = lane >> 2, tig = lane & 3;
    const int bh = blockIdx.x;
    const int qblk = (gridDim.y - 1) - blockIdx.y;   // heaviest blocks first
    const int q0 = qblk * 256;
    const int tmax = 4 * qblk + 3;
    const __half* kbase = kh + (size_t)bh * SS * HD;
    const __half* vbase = vh + (size_t)bh * SS * HD;

#define HISSUE(t) do {                                                             \
    const int _st = (t) & 1;                                                       \
    const int _k0 = (t) * 64;                                                      \
    const int _r = tid >> 3;                                                       \
    const int _c = (tid & 7) * 16;                                                 \
    cp_async16(sb + HKOFF(_st) + (uint32_t)(_r * 144 + _c),                        \
               (const char*)(kbase + (size_t)(_k0 + _r) * HD) + _c);               \
    cp_async16(sb + HVOFF(_st) + (uint32_t)(_r * 144 + _c),                        \
               (const char*)(vbase + (size_t)(_k0 + _r) * HD) + _c);               \
    CP_COMMIT();                                                                   \
} while (0)

    // stage Q (256x64 fp16, pre-scaled) into the P buffer
    {
        const __half* qb = qh + ((size_t)bh * SS + q0) * HD;
#pragma unroll
        for (int i = 0; i < 4; i++) {
            const int f = tid + 512 * i;
            const int r = f >> 3;
            const int c = (f & 7) * 16;
            cp_async16(sb + HPOFF + (uint32_t)(r * 144 + c),
                       (const char*)(qb + (size_t)r * HD) + c);
        }
        CP_COMMIT();
    }
    HISSUE(0);
    CP_WAIT(1);
    __syncthreads();

    const int r0 = w * 16 + g;                       // 0..255
    const uint32_t a_lane = (uint32_t)((w * 16 + ((lane >> 3) & 1) * 8 + (lane & 7)) * 144
                                       + ((lane >> 4) & 1) * 16);
    const uint32_t k_lane = (uint32_t)((((lane >> 4) & 1) * 8 + (lane & 7)) * 144
                                       + ((lane >> 3) & 1) * 16);
    const uint32_t v_lane = (uint32_t)((((lane >> 3) & 1) * 8 + (lane & 7)) * 144
                                       + ((lane >> 4) & 1) * 16);

    uint32_t qa[4][4];
#pragma unroll
    for (int kc = 0; kc < 4; kc++)
        LDSM_X4(qa[kc][0], qa[kc][1], qa[kc][2], qa[kc][3],
                sb + HPOFF + a_lane + kc * 32);
    __syncthreads();       // Q reads done before P overwrites

    float o[8][4];
#pragma unroll
    for (int i = 0; i < 8; i++)
#pragma unroll
        for (int j = 0; j < 4; j++) o[i][j] = 0.f;
    float m0 = -1e30f, m1 = -1e30f, l0 = 0.f, l1 = 0.f;

    for (int t = 0; t <= tmax; t++) {
        const int st = t & 1;
        CP_WAIT(0);
        __syncthreads();
        if (t < tmax) HISSUE(t + 1);

        float s[8][4];
#pragma unroll
        for (int i = 0; i < 8; i++)
#pragma unroll
            for (int j = 0; j < 4; j++) s[i][j] = 0.f;

#pragma unroll
        for (int kc = 0; kc < 4; kc++) {
            uint32_t kb[8][2];
#pragma unroll
            for (int ntp = 0; ntp < 4; ntp++)
                LDSM_X4(kb[2 * ntp][0], kb[2 * ntp][1],
                        kb[2 * ntp + 1][0], kb[2 * ntp + 1][1],
                        sb + HKOFF(st) + k_lane + (uint32_t)(ntp * 16 * 144) + kc * 32);
#pragma unroll
            for (int nt = 0; nt < 8; nt++)
                mma_f16(s[nt], qa[kc], kb[nt]);
        }

        if (t >= 4 * qblk) {           // causal mask on the last 4 key tiles
            const int qg0 = q0 + r0;
            const int qg1 = qg0 + 8;
            const int kb0 = t * 64;
#pragma unroll
            for (int nt = 0; nt < 8; nt++) {
                const int col = kb0 + 8 * nt + 2 * tig;
                if (col > qg0)     s[nt][0] = -1e30f;
                if (col + 1 > qg0) s[nt][1] = -1e30f;
                if (col > qg1)     s[nt][2] = -1e30f;
                if (col + 1 > qg1) s[nt][3] = -1e30f;
            }
        }

        float mx0 = -1e30f, mx1 = -1e30f;
#pragma unroll
        for (int nt = 0; nt < 8; nt++) {
            mx0 = fmaxf(mx0, fmaxf(s[nt][0], s[nt][1]));
            mx1 = fmaxf(mx1, fmaxf(s[nt][2], s[nt][3]));
        }
        mx0 = fmaxf(mx0, __shfl_xor_sync(0xffffffffu, mx0, 1));
        mx0 = fmaxf(mx0, __shfl_xor_sync(0xffffffffu, mx0, 2));
        mx1 = fmaxf(mx1, __shfl_xor_sync(0xffffffffu, mx1, 1));
        mx1 = fmaxf(mx1, __shfl_xor_sync(0xffffffffu, mx1, 2));

        const float mn0 = fmaxf(m0, mx0);
        const float mn1 = fmaxf(m1, mx1);
        const float a0 = __expf(m0 - mn0);
        const float a1 = __expf(m1 - mn1);
        m0 = mn0; m1 = mn1;
        l0 *= a0; l1 *= a1;
#pragma unroll
        for (int nt = 0; nt < 8; nt++) {
            o[nt][0] *= a0; o[nt][1] *= a0;
            o[nt][2] *= a1; o[nt][3] *= a1;
        }

        __half* Ps = (__half*)(smc + HPOFF);
        float rs0 = 0.f, rs1 = 0.f;
#pragma unroll
        for (int nt = 0; nt < 8; nt++) {
            const float p0 = __expf(s[nt][0] - mn0);
            const float p1 = __expf(s[nt][1] - mn0);
            const float p2 = __expf(s[nt][2] - mn1);
            const float p3 = __expf(s[nt][3] - mn1);
            rs0 += p0 + p1;
            rs1 += p2 + p3;
            *(__half2*)(Ps + r0 * 72 + 8 * nt + 2 * tig) = __floats2half2_rn(p0, p1);
            *(__half2*)(Ps + (r0 + 8) * 72 + 8 * nt + 2 * tig) = __floats2half2_rn(p2, p3);
        }
        rs0 += __shfl_xor_sync(0xffffffffu, rs0, 1);
        rs0 += __shfl_xor_sync(0xffffffffu, rs0, 2);
        rs1 += __shfl_xor_sync(0xffffffffu, rs1, 1);
        rs1 += __shfl_xor_sync(0xffffffffu, rs1, 2);
        l0 += rs0; l1 += rs1;

        __syncwarp();      // P rows are warp-private

#pragma unroll
        for (int kc = 0; kc < 4; kc++) {
            uint32_t pa[4];
            LDSM_X4(pa[0], pa[1], pa[2], pa[3], sb + HPOFF + a_lane + kc * 32);
            uint32_t vb[8][2];
#pragma unroll
            for (int ntp = 0; ntp < 4; ntp++)
                LDSM_X4_T(vb[2 * ntp][0], vb[2 * ntp][1],
                          vb[2 * ntp + 1][0], vb[2 * ntp + 1][1],
                          sb + HVOFF(st) + v_lane + (uint32_t)(kc * 16 * 144) + ntp * 32);
#pragma unroll
            for (int nt = 0; nt < 8; nt++)
                mma_f16(o[nt], pa, vb[nt]);
        }
    }

    const float inv0 = 1.0f / l0;
    const float inv1 = 1.0f / l1;
    const int b = bh >> 4, h = bh & 15;
    const size_t base0 = ((size_t)b * SS + q0 + r0) * DD + h * 64;
    const size_t base1 = ((size_t)b * SS + q0 + r0 + 8) * DD + h * 64;
#pragma unroll
    for (int nt = 0; nt < 8; nt++) {
        const int col = 8 * nt + 2 * tig;
        *(__half2*)(g_a + base0 + col) = __floats2half2_rn(o[nt][0] * inv0, o[nt][1] * inv0);
        *(__half2*)(g_a + base1 + col) = __floats2half2_rn(o[nt][2] * inv1, o[nt][3] * inv1);
    }
}

// ---------------------------------------------------------------------------
extern "C" void kernel_launch(void* const* d_in, const int* in_sizes, int n_in,
                              void* d_out, int out_size)
{
    const float* x      = (const float*)d_in[0];
    const float* w_attn = (const float*)d_in[1];
    const float* b_attn = (const float*)d_in[2];
    const float* w_proj = (const float*)d_in[3];
    const float* b_proj = (const float*)d_in[4];

    float* out  = (float*)d_out;
    float* kout = out + (size_t)BB * SS * DD;
    float* vout = kout + (size_t)BB * HH * SS * HD;

    __half *xh, *wah, *wth, *ah, *qh, *krh, *vrh;
    cudaGetSymbolAddress((void**)&xh, g_xh);
    cudaGetSymbolAddress((void**)&wah, g_wah);
    cudaGetSymbolAddress((void**)&wth, g_wth);
    cudaGetSymbolAddress((void**)&ah, g_a);
    cudaGetSymbolAddress((void**)&qh, g_qh);
    cudaGetSymbolAddress((void**)&krh, g_krh);
    cudaGetSymbolAddress((void**)&vrh, g_vrh);

    cudaFuncSetAttribute(mma_gemm_h<0>, cudaFuncAttributeMaxDynamicSharedMemorySize, GEMM_SMEM);
    cudaFuncSetAttribute(mma_gemm_h<1>, cudaFuncAttributeMaxDynamicSharedMemorySize, GEMM_SMEM);
    cudaFuncSetAttribute(attn_h, cudaFuncAttributeMaxDynamicSharedMemorySize, ATT_SMEM);

    // Fused prep: transpose+round w_proj, round x, round w_attn
    prep_kernel<<<1024, 256>>>((const float4*)x, (uint2*)xh, BB * SS * DD / 4,
                               (const float4*)w_attn, (uint2*)wah, 3 * DD * DD / 4,
                               w_proj, wth);

    // QKV GEMM (fp16): q*0.125->g_qh, k/v exact->present + fp16 copies
    mma_gemm_h<1><<<dim3(3 * DD / 128, BB * SS / 128), 256, GEMM_SMEM>>>(
        xh, wah, b_attn, nullptr, kout, vout);

    // fp16 flash attention (256 queries/CTA) -> g_a
    attn_h<<<dim3(BB * HH, SS / 256), 512, ATT_SMEM>>>(qh, krh, vrh);

    // Proj GEMM (fp16) -> out
    mma_gemm_h<0><<<dim3(DD / 128, BB * SS / 128), 256, GEMM_SMEM>>>(
        ah, wth, b_proj, out, nullptr, nullptr);
}

// round 16
// speedup vs baseline: 1.0335x; 1.0335x over previous
#include <cuda_runtime.h>
#include <cuda_fp16.h>
#include <cstdint>

#define BB 4
#define SS 2048
#define DD 1024
#define HH 16
#define HD 64

// Scratch (allocation-free)
__device__ __half g_qh[(size_t)BB * HH * SS * HD];  // q fp16, pre-scaled by 0.125
__device__ __half g_krh[(size_t)BB * HH * SS * HD]; // k fp16 (attention input)
__device__ __half g_vrh[(size_t)BB * HH * SS * HD]; // v fp16 (attention input)
__device__ __half g_a[(size_t)BB * SS * DD];        // attention out (fp16, proj input)
__device__ __half g_xh[(size_t)BB * SS * DD];       // x in fp16
__device__ __half g_wah[(size_t)3 * DD * DD];       // w_attn in fp16
__device__ __half g_wth[(size_t)DD * DD];           // w_proj^T in fp16

// ---------------------------------------------------------------------------
__device__ __forceinline__ uint32_t smem_u32(const void* p) {
    uint32_t a;
    asm("{ .reg .u64 t; cvta.to.shared.u64 t, %1; cvt.u32.u64 %0, t; }"
        : "=r"(a) : "l"(p));
    return a;
}
__device__ __forceinline__ void cp_async16(uint32_t dst, const void* src) {
    asm volatile("cp.async.cg.shared.global [%0], [%1], 16;" :: "r"(dst), "l"(src));
}
#define CP_COMMIT() asm volatile("cp.async.commit_group;" ::: "memory")
#define CP_WAIT(n)  asm volatile("cp.async.wait_group %0;" :: "n"(n) : "memory")

__device__ __forceinline__ void mma_f16(float* c, const uint32_t* a, const uint32_t* b) {
    asm volatile(
        "mma.sync.aligned.m16n8k16.row.col.f32.f16.f16.f32 "
        "{%0,%1,%2,%3}, {%4,%5,%6,%7}, {%8,%9}, {%0,%1,%2,%3};"
        : "+f"(c[0]), "+f"(c[1]), "+f"(c[2]), "+f"(c[3])
        : "r"(a[0]), "r"(a[1]), "r"(a[2]), "r"(a[3]), "r"(b[0]), "r"(b[1]));
}
#define LDSM_X4(r0, r1, r2, r3, addr) \
    asm volatile("ldmatrix.sync.aligned.m8n8.x4.shared.b16 {%0,%1,%2,%3}, [%4];" \
        : "=r"(r0), "=r"(r1), "=r"(r2), "=r"(r3) : "r"(addr))
#define LDSM_X4_T(r0, r1, r2, r3, addr) \
    asm volatile("ldmatrix.sync.aligned.m8n8.x4.trans.shared.b16 {%0,%1,%2,%3}, [%4];" \
        : "=r"(r0), "=r"(r1), "=r"(r2), "=r"(r3) : "r"(addr))

// ---------------------------------------------------------------------------
// Fused prep: w_proj transpose+round (per-block tile) + x / w_attn fp16
// conversion (grid-stride). Grid must be exactly 1024 blocks x 256 threads.
// ---------------------------------------------------------------------------
__global__ __launch_bounds__(256) void prep_kernel(
    const float4* __restrict__ x4, uint2* __restrict__ xh4, int n4x,
    const float4* __restrict__ wa4, uint2* __restrict__ wah4, int n4w,
    const float* __restrict__ wp, __half* __restrict__ wth)
{
    __shared__ float t[32][33];
    const int tid = threadIdx.x;

    // --- w_proj [K,N] -> wth [N,K] (fp16). 1024 blocks = 32x32 tiles.
    {
        const int bx = blockIdx.x & 31;
        const int by = blockIdx.x >> 5;
        const int tx = tid & 31, ty = tid >> 5;
        const int k0 = by * 32, n0 = bx * 32;
#pragma unroll
        for (int i = ty; i < 32; i += 8)
            t[i][tx] = wp[(size_t)(k0 + i) * DD + n0 + tx];
        __syncthreads();
#pragma unroll
        for (int i = ty; i < 32; i += 8)
            wth[(size_t)(n0 + i) * DD + k0 + tx] = __float2half_rn(t[tx][i]);
    }

    // --- x -> fp16
    const int stride = gridDim.x * blockDim.x;
    for (int i = blockIdx.x * 256 + tid; i < n4x; i += stride) {
        float4 v = x4[i];
        __half2 h0 = __floats2half2_rn(v.x, v.y);
        __half2 h1 = __floats2half2_rn(v.z, v.w);
        uint2 o; o.x = *(uint32_t*)&h0; o.y = *(uint32_t*)&h1;
        xh4[i] = o;
    }
    // --- w_attn -> fp16
    for (int i = blockIdx.x * 256 + tid; i < n4w; i += stride) {
        float4 v = wa4[i];
        __half2 h0 = __floats2half2_rn(v.x, v.y);
        __half2 h1 = __floats2half2_rn(v.z, v.w);
        uint2 o; o.x = *(uint32_t*)&h0; o.y = *(uint32_t*)&h1;
        wah4[i] = o;
    }
}

// ---------------------------------------------------------------------------
// fp16 mma.sync GEMM: 128x128 CTA tile, 32x64 warp tile, BK=64 halfs,
// 3-stage cp.async, ldmatrix fragments double-buffered, 2 CTAs/SM.
// MODE 0: C -> out0. MODE 1: q*0.125->g_qh, k->out1+g_krh, v->out2+g_vrh.
// ---------------------------------------------------------------------------
#define KDIM 1024
#define NCHUNK 16
#define STG_BYTES (256 * 144)
#define GEMM_SMEM (3 * STG_BYTES)

template <int MODE>
__global__ __launch_bounds__(256, 2) void mma_gemm_h(
    const __half* __restrict__ A, const __half* __restrict__ Bm,
    const float* __restrict__ bias,
    float* __restrict__ out0, float* __restrict__ out1, float* __restrict__ out2)
{
    extern __shared__ __half smh[];
    const uint32_t sbase = smem_u32(smh);
    const int tid = threadIdx.x;
    const int wid = tid >> 5;
    const int lane = tid & 31;
    const int g = lane >> 2;
    const int tig = lane & 3;
    const int m0 = blockIdx.y * 128;
    const int n0 = blockIdx.x * 128;
    const int wm = (wid & 3) * 32;
    const int wn = (wid >> 2) * 64;

    const uint32_t a_lane = (uint32_t)((((lane >> 3) & 1) * 8 + (lane & 7)) * 144
                                       + ((lane >> 4) & 1) * 16);
    const uint32_t b_lane = (uint32_t)((((lane >> 4) & 1) * 8 + (lane & 7)) * 144
                                       + ((lane >> 3) & 1) * 16);

    float c[2][8][4];
#pragma unroll
    for (int i = 0; i < 2; i++)
#pragma unroll
        for (int j = 0; j < 8; j++)
#pragma unroll
            for (int k = 0; k < 4; k++) c[i][j][k] = 0.f;

    const int lr = tid >> 1;
    const int lcb = (tid & 1) * 64;
    const char* Agc = (const char*)(A + (size_t)(m0 + lr) * KDIM) + lcb;
    const char* Bgc = (const char*)(Bm + (size_t)(n0 + lr) * KDIM) + lcb;

#define ISSUE(chunk) do {                                                           \
    const uint32_t _as = sbase + (uint32_t)((chunk) % 3) * STG_BYTES;               \
    const uint32_t _bs = _as + 128u * 144u;                                         \
    const int _kb = (chunk) * 128;                                                  \
    _Pragma("unroll")                                                               \
    for (int _i = 0; _i < 4; _i++)                                                  \
        cp_async16(_as + (uint32_t)(lr * 144 + lcb + _i * 16), Agc + _kb + _i * 16);\
    _Pragma("unroll")                                                               \
    for (int _i = 0; _i < 4; _i++)                                                  \
        cp_async16(_bs + (uint32_t)(lr * 144 + lcb + _i * 16), Bgc + _kb + _i * 16);\
    CP_COMMIT();                                                                    \
} while (0)

#define LOAD_FRAGS(buf, ks) do {                                                    \
    _Pragma("unroll")                                                               \
    for (int _mt = 0; _mt < 2; _mt++)                                               \
        LDSM_X4(af[buf][_mt][0], af[buf][_mt][1], af[buf][_mt][2], af[buf][_mt][3], \
                aBase + (uint32_t)((wm + _mt * 16) * 144) + a_lane + (ks) * 32);    \
    _Pragma("unroll")                                                               \
    for (int _np = 0; _np < 4; _np++)                                               \
        LDSM_X4(bf[buf][2 * _np][0], bf[buf][2 * _np][1],                           \
                bf[buf][2 * _np + 1][0], bf[buf][2 * _np + 1][1],                   \
                bBase + (uint32_t)((wn + _np * 16) * 144) + b_lane + (ks) * 32);    \
} while (0)

    ISSUE(0);
    ISSUE(1);

    for (int ch = 0; ch < NCHUNK; ch++) {
        if (ch + 1 < NCHUNK) { CP_WAIT(1); } else { CP_WAIT(0); }
        __syncthreads();
        if (ch + 2 < NCHUNK) ISSUE(ch + 2);

        const uint32_t aBase = sbase + (uint32_t)(ch % 3) * STG_BYTES;
        const uint32_t bBase = aBase + 128u * 144u;

        uint32_t af[2][2][4], bf[2][8][2];
        LOAD_FRAGS(0, 0);
#pragma unroll
        for (int ks = 0; ks < 4; ks++) {
            const int cur = ks & 1;
            if (ks < 3) LOAD_FRAGS((ks + 1) & 1, ks + 1);
#pragma unroll
            for (int mt = 0; mt < 2; mt++)
#pragma unroll
                for (int nt = 0; nt < 8; nt++)
                    mma_f16(c[mt][nt], af[cur][mt], bf[cur][nt]);
        }
    }

#pragma unroll
    for (int mt = 0; mt < 2; mt++) {
        const int row0 = m0 + wm + mt * 16 + g;
        const int row1 = row0 + 8;
#pragma unroll
        for (int nt = 0; nt < 8; nt++) {
            const int n = n0 + wn + nt * 8 + 2 * tig;
            const float2 bv = *(const float2*)(bias + n);
            float2 v0, v1;
            v0.x = c[mt][nt][0] + bv.x; v0.y = c[mt][nt][1] + bv.y;
            v1.x = c[mt][nt][2] + bv.x; v1.y = c[mt][nt][3] + bv.y;
            if (MODE == 0) {
                *(float2*)(out0 + (size_t)row0 * DD + n) = v0;
                *(float2*)(out0 + (size_t)row1 * DD + n) = v1;
            } else {
                const int part = n >> 10;
                const int hc = n & (DD - 1);
                const int h = hc >> 6;
                const int d = hc & 63;
                const int b0_ = row0 >> 11, s0_ = row0 & (SS - 1);
                const int b1_ = row1 >> 11, s1_ = row1 & (SS - 1);
                const size_t d0 = (((size_t)(b0_ * HH + h)) * SS + s0_) * HD + d;
                const size_t d1 = (((size_t)(b1_ * HH + h)) * SS + s1_) * HD + d;
                if (part == 0) {
                    *(__half2*)(g_qh + d0) = __floats2half2_rn(v0.x * 0.125f, v0.y * 0.125f);
                    *(__half2*)(g_qh + d1) = __floats2half2_rn(v1.x * 0.125f, v1.y * 0.125f);
                } else if (part == 1) {
                    *(float2*)(out1 + d0) = v0;       // exact -> present
                    *(float2*)(out1 + d1) = v1;
                    *(__half2*)(g_krh + d0) = __floats2half2_rn(v0.x, v0.y);
                    *(__half2*)(g_krh + d1) = __floats2half2_rn(v1.x, v1.y);
                } else {
                    *(float2*)(out2 + d0) = v0;
                    *(float2*)(out2 + d1) = v1;
                    *(__half2*)(g_vrh + d0) = __floats2half2_rn(v0.x, v0.y);
                    *(__half2*)(g_vrh + d1) = __floats2half2_rn(v1.x, v1.y);
                }
            }
        }
    }
}

// ---------------------------------------------------------------------------
// fp16 tensor-core causal flash attention with ldmatrix.
// CTA: 256 threads (8 warps), 128 queries; key tiles of 64, 2 stages, 2 CTA/SM,
// heaviest q-blocks scheduled first.
// ---------------------------------------------------------------------------
#define HKOFF(s) ((uint32_t)(s) * 9216u)
#define HVOFF(s) (18432u + (uint32_t)(s) * 9216u)
#define HPOFF 36864u
#define ATT_SMEM 55296

__global__ __launch_bounds__(256, 2) void attn_h(
    const __half* __restrict__ qh, const __half* __restrict__ kh,
    const __half* __restrict__ vh)
{
    extern __shared__ char smc[];
    const uint32_t sb = smem_u32(smc);
    const int tid = threadIdx.x;
    const int w = tid >> 5, lane = tid & 31;
    const int g = lane >> 2, tig = lane & 3;
    const int bh = blockIdx.x;
    const int qblk = (gridDim.y - 1) - blockIdx.y;   // heaviest blocks first
    const int q0 = qblk * 128;
    const int tmax = 2 * qblk + 1;
    const __half* kbase = kh + (size_t)bh * SS * HD;
    const __half* vbase = vh + (size_t)bh * SS * HD;

#define HISSUE(t) do {                                                             \
    const int _st = (t) & 1;                                                       \
    const int _k0 = (t) * 64;                                                      \
    _Pragma("unroll")                                                              \
    for (int _i = 0; _i < 2; _i++) {                                               \
        const int _f = tid + 256 * _i;                                             \
        const int _r = _f >> 3;                                                    \
        const int _c = (_f & 7) * 16;                                              \
        cp_async16(sb + HKOFF(_st) + (uint32_t)(_r * 144 + _c),                    \
                   (const char*)(kbase + (size_t)(_k0 + _r) * HD) + _c);           \
        cp_async16(sb + HVOFF(_st) + (uint32_t)(_r * 144 + _c),                    \
                   (const char*)(vbase + (size_t)(_k0 + _r) * HD) + _c);           \
    }                                                                              \
    CP_COMMIT();                                                                   \
} while (0)

    {
        const __half* qb = qh + ((size_t)bh * SS + q0) * HD;
#pragma unroll
        for (int i = 0; i < 4; i++) {
            const int f = tid + 256 * i;
            const int r = f >> 3;
            const int c = (f & 7) * 16;
            cp_async16(sb + HPOFF + (uint32_t)(r * 144 + c),
                       (const char*)(qb + (size_t)r * HD) + c);
        }
        CP_COMMIT();
    }
    HISSUE(0);
    CP_WAIT(1);
    __syncthreads();

    const int r0 = w * 16 + g;
    const uint32_t a_lane = (uint32_t)((w * 16 + ((lane >> 3) & 1) * 8 + (lane & 7)) * 144
                                       + ((lane >> 4) & 1) * 16);
    const uint32_t k_lane = (uint32_t)((((lane >> 4) & 1) * 8 + (lane & 7)) * 144
                                       + ((lane >> 3) & 1) * 16);
    const uint32_t v_lane = (uint32_t)((((lane >> 3) & 1) * 8 + (lane & 7)) * 144
                                       + ((lane >> 4) & 1) * 16);

    uint32_t qa[4][4];
#pragma unroll
    for (int kc = 0; kc < 4; kc++)
        LDSM_X4(qa[kc][0], qa[kc][1], qa[kc][2], qa[kc][3],
                sb + HPOFF + a_lane + kc * 32);
    __syncthreads();

    float o[8][4];
#pragma unroll
    for (int i = 0; i < 8; i++)
#pragma unroll
        for (int j = 0; j < 4; j++) o[i][j] = 0.f;
    float m0 = -1e30f, m1 = -1e30f, l0 = 0.f, l1 = 0.f;

    for (int t = 0; t <= tmax; t++) {
        const int st = t & 1;
        CP_WAIT(0);
        __syncthreads();
        if (t < tmax) HISSUE(t + 1);

        float s[8][4];
#pragma unroll
        for (int i = 0; i < 8; i++)
#pragma unroll
            for (int j = 0; j < 4; j++) s[i][j] = 0.f;

#pragma unroll
        for (int kc = 0; kc < 4; kc++) {
            uint32_t kb[8][2];
#pragma unroll
            for (int ntp = 0; ntp < 4; ntp++)
                LDSM_X4(kb[2 * ntp][0], kb[2 * ntp][1],
                        kb[2 * ntp + 1][0], kb[2 * ntp + 1][1],
                        sb + HKOFF(st) + k_lane + (uint32_t)(ntp * 16 * 144) + kc * 32);
#pragma unroll
            for (int nt = 0; nt < 8; nt++)
                mma_f16(s[nt], qa[kc], kb[nt]);
        }

        if (t >= 2 * qblk) {
            const int qg0 = q0 + r0;
            const int qg1 = qg0 + 8;
            const int kb0 = t * 64;
#pragma unroll
            for (int nt = 0; nt < 8; nt++) {
                const int col = kb0 + 8 * nt + 2 * tig;
                if (col > qg0)     s[nt][0] = -1e30f;
                if (col + 1 > qg0) s[nt][1] = -1e30f;
                if (col > qg1)     s[nt][2] = -1e30f;
                if (col + 1 > qg1) s[nt][3] = -1e30f;
            }
        }

        float mx0 = -1e30f, mx1 = -1e30f;
#pragma unroll
        for (int nt = 0; nt < 8; nt++) {
            mx0 = fmaxf(mx0, fmaxf(s[nt][0], s[nt][1]));
            mx1 = fmaxf(mx1, fmaxf(s[nt][2], s[nt][3]));
        }
        mx0 = fmaxf(mx0, __shfl_xor_sync(0xffffffffu, mx0, 1));
        mx0 = fmaxf(mx0, __shfl_xor_sync(0xffffffffu, mx0, 2));
        mx1 = fmaxf(mx1, __shfl_xor_sync(0xffffffffu, mx1, 1));
        mx1 = fmaxf(mx1, __shfl_xor_sync(0xffffffffu, mx1, 2));

        const float mn0 = fmaxf(m0, mx0);
        const float mn1 = fmaxf(m1, mx1);
        const float a0 = __expf(m0 - mn0);
        const float a1 = __expf(m1 - mn1);
        m0 = mn0; m1 = mn1;
        l0 *= a0; l1 *= a1;
#pragma unroll
        for (int nt = 0; nt < 8; nt++) {
            o[nt][0] *= a0; o[nt][1] *= a0;
            o[nt][2] *= a1; o[nt][3] *= a1;
        }

        __half* Ps = (__half*)(smc + HPOFF);
        float rs0 = 0.f, rs1 = 0.f;
#pragma unroll
        for (int nt = 0; nt < 8; nt++) {
            const float p0 = __expf(s[nt][0] - mn0);
            const float p1 = __expf(s[nt][1] - mn0);
            const float p2 = __expf(s[nt][2] - mn1);
            const float p3 = __expf(s[nt][3] - mn1);
            rs0 += p0 + p1;
            rs1 += p2 + p3;
            *(__half2*)(Ps + r0 * 72 + 8 * nt + 2 * tig) = __floats2half2_rn(p0, p1);
            *(__half2*)(Ps + (r0 + 8) * 72 + 8 * nt + 2 * tig) = __floats2half2_rn(p2, p3);
        }
        rs0 += __shfl_xor_sync(0xffffffffu, rs0, 1);
        rs0 += __shfl_xor_sync(0xffffffffu, rs0, 2);
        rs1 += __shfl_xor_sync(0xffffffffu, rs1, 1);
        rs1 += __shfl_xor_sync(0xffffffffu, rs1, 2);
        l0 += rs0; l1 += rs1;

        __syncwarp();

#pragma unroll
        for (int kc = 0; kc < 4; kc++) {
            uint32_t pa[4];
            LDSM_X4(pa[0], pa[1], pa[2], pa[3], sb + HPOFF + a_lane + kc * 32);
            uint32_t vb[8][2];
#pragma unroll
            for (int ntp = 0; ntp < 4; ntp++)
                LDSM_X4_T(vb[2 * ntp][0], vb[2 * ntp][1],
                          vb[2 * ntp + 1][0], vb[2 * ntp + 1][1],
                          sb + HVOFF(st) + v_lane + (uint32_t)(kc * 16 * 144) + ntp * 32);
#pragma unroll
            for (int nt = 0; nt < 8; nt++)
                mma_f16(o[nt], pa, vb[nt]);
        }
    }

    const float inv0 = 1.0f / l0;
    const float inv1 = 1.0f / l1;
    const int b = bh >> 4, h = bh & 15;
    const size_t base0 = ((size_t)b * SS + q0 + r0) * DD + h * 64;
    const size_t base1 = ((size_t)b * SS + q0 + r0 + 8) * DD + h * 64;
#pragma unroll
    for (int nt = 0; nt < 8; nt++) {
        const int col = 8 * nt + 2 * tig;
        *(__half2*)(g_a + base0 + col) = __floats2half2_rn(o[nt][0] * inv0, o[nt][1] * inv0);
        *(__half2*)(g_a + base1 + col) = __floats2half2_rn(o[nt][2] * inv1, o[nt][3] * inv1);
    }
}

// ---------------------------------------------------------------------------
extern "C" void kernel_launch(void* const* d_in, const int* in_sizes, int n_in,
                              void* d_out, int out_size)
{
    const float* x      = (const float*)d_in[0];
    const float* w_attn = (const float*)d_in[1];
    const float* b_attn = (const float*)d_in[2];
    const float* w_proj = (const float*)d_in[3];
    const float* b_proj = (const float*)d_in[4];

    float* out  = (float*)d_out;
    float* kout = out + (size_t)BB * SS * DD;
    float* vout = kout + (size_t)BB * HH * SS * HD;

    __half *xh, *wah, *wth, *ah, *qh, *krh, *vrh;
    cudaGetSymbolAddress((void**)&xh, g_xh);
    cudaGetSymbolAddress((void**)&wah, g_wah);
    cudaGetSymbolAddress((void**)&wth, g_wth);
    cudaGetSymbolAddress((void**)&ah, g_a);
    cudaGetSymbolAddress((void**)&qh, g_qh);
    cudaGetSymbolAddress((void**)&krh, g_krh);
    cudaGetSymbolAddress((void**)&vrh, g_vrh);

    cudaFuncSetAttribute(mma_gemm_h<0>, cudaFuncAttributeMaxDynamicSharedMemorySize, GEMM_SMEM);
    cudaFuncSetAttribute(mma_gemm_h<1>, cudaFuncAttributeMaxDynamicSharedMemorySize, GEMM_SMEM);
    cudaFuncSetAttribute(attn_h, cudaFuncAttributeMaxDynamicSharedMemorySize, ATT_SMEM);

    // Fused prep: transpose+round w_proj, round x, round w_attn
    prep_kernel<<<1024, 256>>>((const float4*)x, (uint2*)xh, BB * SS * DD / 4,
                               (const float4*)w_attn, (uint2*)wah, 3 * DD * DD / 4,
                               w_proj, wth);

    // QKV GEMM (fp16): q*0.125->g_qh, k/v exact->present + fp16 copies
    mma_gemm_h<1><<<dim3(3 * DD / 128, BB * SS / 128), 256, GEMM_SMEM>>>(
        xh, wah, b_attn, nullptr, kout, vout);

    // fp16 flash attention (128 queries/CTA, 2 CTA/SM) -> g_a
    attn_h<<<dim3(BB * HH, SS / 128), 256, ATT_SMEM>>>(qh, krh, vrh);

    // Proj GEMM (fp16) -> out
    mma_gemm_h<0><<<dim3(DD / 128, BB * SS / 128), 256, GEMM_SMEM>>>(
        ah, wth, b_proj, out, nullptr, nullptr);
}

// round 17
// speedup vs baseline: 1.0363x; 1.0028x over previous
#include <cuda_runtime.h>
#include <cuda_fp16.h>
#include <cstdint>

#define BB 4
#define SS 2048
#define DD 1024
#define HH 16
#define HD 64

// Scratch (allocation-free)
__device__ __half g_qh[(size_t)BB * HH * SS * HD];  // q fp16, pre-scaled by 0.125*log2(e)
__device__ __half g_krh[(size_t)BB * HH * SS * HD]; // k fp16 (attention input)
__device__ __half g_vrh[(size_t)BB * HH * SS * HD]; // v fp16 (attention input)
__device__ __half g_a[(size_t)BB * SS * DD];        // attention out (fp16, proj input)
__device__ __half g_xh[(size_t)BB * SS * DD];       // x in fp16
__device__ __half g_wah[(size_t)3 * DD * DD];       // w_attn in fp16
__device__ __half g_wth[(size_t)DD * DD];           // w_proj^T in fp16

// ---------------------------------------------------------------------------
__device__ __forceinline__ uint32_t smem_u32(const void* p) {
    uint32_t a;
    asm("{ .reg .u64 t; cvta.to.shared.u64 t, %1; cvt.u32.u64 %0, t; }"
        : "=r"(a) : "l"(p));
    return a;
}
__device__ __forceinline__ void cp_async16(uint32_t dst, const void* src) {
    asm volatile("cp.async.cg.shared.global [%0], [%1], 16;" :: "r"(dst), "l"(src));
}
#define CP_COMMIT() asm volatile("cp.async.commit_group;" ::: "memory")
#define CP_WAIT(n)  asm volatile("cp.async.wait_group %0;" :: "n"(n) : "memory")

__device__ __forceinline__ void mma_f16(float* c, const uint32_t* a, const uint32_t* b) {
    asm volatile(
        "mma.sync.aligned.m16n8k16.row.col.f32.f16.f16.f32 "
        "{%0,%1,%2,%3}, {%4,%5,%6,%7}, {%8,%9}, {%0,%1,%2,%3};"
        : "+f"(c[0]), "+f"(c[1]), "+f"(c[2]), "+f"(c[3])
        : "r"(a[0]), "r"(a[1]), "r"(a[2]), "r"(a[3]), "r"(b[0]), "r"(b[1]));
}
#define LDSM_X4(r0, r1, r2, r3, addr) \
    asm volatile("ldmatrix.sync.aligned.m8n8.x4.shared.b16 {%0,%1,%2,%3}, [%4];" \
        : "=r"(r0), "=r"(r1), "=r"(r2), "=r"(r3) : "r"(addr))
#define LDSM_X4_T(r0, r1, r2, r3, addr) \
    asm volatile("ldmatrix.sync.aligned.m8n8.x4.trans.shared.b16 {%0,%1,%2,%3}, [%4];" \
        : "=r"(r0), "=r"(r1), "=r"(r2), "=r"(r3) : "r"(addr))

// ---------------------------------------------------------------------------
// Fused prep: w_proj transpose+round (per-block tile) + x / w_attn fp16
// conversion (grid-stride). Grid must be exactly 1024 blocks x 256 threads.
// ---------------------------------------------------------------------------
__global__ __launch_bounds__(256) void prep_kernel(
    const float4* __restrict__ x4, uint2* __restrict__ xh4, int n4x,
    const float4* __restrict__ wa4, uint2* __restrict__ wah4, int n4w,
    const float* __restrict__ wp, __half* __restrict__ wth)
{
    __shared__ float t[32][33];
    const int tid = threadIdx.x;

    // --- w_proj [K,N] -> wth [N,K] (fp16). 1024 blocks = 32x32 tiles.
    {
        const int bx = blockIdx.x & 31;
        const int by = blockIdx.x >> 5;
        const int tx = tid & 31, ty = tid >> 5;
        const int k0 = by * 32, n0 = bx * 32;
#pragma unroll
        for (int i = ty; i < 32; i += 8)
            t[i][tx] = wp[(size_t)(k0 + i) * DD + n0 + tx];
        __syncthreads();
#pragma unroll
        for (int i = ty; i < 32; i += 8)
            wth[(size_t)(n0 + i) * DD + k0 + tx] = __float2half_rn(t[tx][i]);
    }

    // --- x -> fp16
    const int stride = gridDim.x * blockDim.x;
    for (int i = blockIdx.x * 256 + tid; i < n4x; i += stride) {
        float4 v = x4[i];
        __half2 h0 = __floats2half2_rn(v.x, v.y);
        __half2 h1 = __floats2half2_rn(v.z, v.w);
        uint2 o; o.x = *(uint32_t*)&h0; o.y = *(uint32_t*)&h1;
        xh4[i] = o;
    }
    // --- w_attn -> fp16
    for (int i = blockIdx.x * 256 + tid; i < n4w; i += stride) {
        float4 v = wa4[i];
        __half2 h0 = __floats2half2_rn(v.x, v.y);
        __half2 h1 = __floats2half2_rn(v.z, v.w);
        uint2 o; o.x = *(uint32_t*)&h0; o.y = *(uint32_t*)&h1;
        wah4[i] = o;
    }
}

// ---------------------------------------------------------------------------
// fp16 mma.sync GEMM: 128x128 CTA tile, 32x64 warp tile, BK=64 halfs,
// 3-stage cp.async, ldmatrix fragments double-buffered, 2 CTAs/SM.
// MODE 0: C -> out0. MODE 1: q*QSCALE->g_qh, k->out1+g_krh, v->out2+g_vrh.
// ---------------------------------------------------------------------------
#define KDIM 1024
#define NCHUNK 16
#define STG_BYTES (256 * 144)
#define GEMM_SMEM (3 * STG_BYTES)
#define QSCALE 0.1803368801111333f   // 0.125 * log2(e): scores land in log2 domain

template <int MODE>
__global__ __launch_bounds__(256, 2) void mma_gemm_h(
    const __half* __restrict__ A, const __half* __restrict__ Bm,
    const float* __restrict__ bias,
    float* __restrict__ out0, float* __restrict__ out1, float* __restrict__ out2)
{
    extern __shared__ __half smh[];
    const uint32_t sbase = smem_u32(smh);
    const int tid = threadIdx.x;
    const int wid = tid >> 5;
    const int lane = tid & 31;
    const int g = lane >> 2;
    const int tig = lane & 3;
    const int m0 = blockIdx.y * 128;
    const int n0 = blockIdx.x * 128;
    const int wm = (wid & 3) * 32;
    const int wn = (wid >> 2) * 64;

    const uint32_t a_lane = (uint32_t)((((lane >> 3) & 1) * 8 + (lane & 7)) * 144
                                       + ((lane >> 4) & 1) * 16);
    const uint32_t b_lane = (uint32_t)((((lane >> 4) & 1) * 8 + (lane & 7)) * 144
                                       + ((lane >> 3) & 1) * 16);

    float c[2][8][4];
#pragma unroll
    for (int i = 0; i < 2; i++)
#pragma unroll
        for (int j = 0; j < 8; j++)
#pragma unroll
            for (int k = 0; k < 4; k++) c[i][j][k] = 0.f;

    const int lr = tid >> 1;
    const int lcb = (tid & 1) * 64;
    const char* Agc = (const char*)(A + (size_t)(m0 + lr) * KDIM) + lcb;
    const char* Bgc = (const char*)(Bm + (size_t)(n0 + lr) * KDIM) + lcb;

#define ISSUE(chunk) do {                                                           \
    const uint32_t _as = sbase + (uint32_t)((chunk) % 3) * STG_BYTES;               \
    const uint32_t _bs = _as + 128u * 144u;                                         \
    const int _kb = (chunk) * 128;                                                  \
    _Pragma("unroll")                                                               \
    for (int _i = 0; _i < 4; _i++)                                                  \
        cp_async16(_as + (uint32_t)(lr * 144 + lcb + _i * 16), Agc + _kb + _i * 16);\
    _Pragma("unroll")                                                               \
    for (int _i = 0; _i < 4; _i++)                                                  \
        cp_async16(_bs + (uint32_t)(lr * 144 + lcb + _i * 16), Bgc + _kb + _i * 16);\
    CP_COMMIT();                                                                    \
} while (0)

#define LOAD_FRAGS(buf, ks) do {                                                    \
    _Pragma("unroll")                                                               \
    for (int _mt = 0; _mt < 2; _mt++)                                               \
        LDSM_X4(af[buf][_mt][0], af[buf][_mt][1], af[buf][_mt][2], af[buf][_mt][3], \
                aBase + (uint32_t)((wm + _mt * 16) * 144) + a_lane + (ks) * 32);    \
    _Pragma("unroll")                                                               \
    for (int _np = 0; _np < 4; _np++)                                               \
        LDSM_X4(bf[buf][2 * _np][0], bf[buf][2 * _np][1],                           \
                bf[buf][2 * _np + 1][0], bf[buf][2 * _np + 1][1],                   \
                bBase + (uint32_t)((wn + _np * 16) * 144) + b_lane + (ks) * 32);    \
} while (0)

    ISSUE(0);
    ISSUE(1);

    for (int ch = 0; ch < NCHUNK; ch++) {
        if (ch + 1 < NCHUNK) { CP_WAIT(1); } else { CP_WAIT(0); }
        __syncthreads();
        if (ch + 2 < NCHUNK) ISSUE(ch + 2);

        const uint32_t aBase = sbase + (uint32_t)(ch % 3) * STG_BYTES;
        const uint32_t bBase = aBase + 128u * 144u;

        uint32_t af[2][2][4], bf[2][8][2];
        LOAD_FRAGS(0, 0);
#pragma unroll
        for (int ks = 0; ks < 4; ks++) {
            const int cur = ks & 1;
            if (ks < 3) LOAD_FRAGS((ks + 1) & 1, ks + 1);
#pragma unroll
            for (int mt = 0; mt < 2; mt++)
#pragma unroll
                for (int nt = 0; nt < 8; nt++)
                    mma_f16(c[mt][nt], af[cur][mt], bf[cur][nt]);
        }
    }

#pragma unroll
    for (int mt = 0; mt < 2; mt++) {
        const int row0 = m0 + wm + mt * 16 + g;
        const int row1 = row0 + 8;
#pragma unroll
        for (int nt = 0; nt < 8; nt++) {
            const int n = n0 + wn + nt * 8 + 2 * tig;
            const float2 bv = *(const float2*)(bias + n);
            float2 v0, v1;
            v0.x = c[mt][nt][0] + bv.x; v0.y = c[mt][nt][1] + bv.y;
            v1.x = c[mt][nt][2] + bv.x; v1.y = c[mt][nt][3] + bv.y;
            if (MODE == 0) {
                *(float2*)(out0 + (size_t)row0 * DD + n) = v0;
                *(float2*)(out0 + (size_t)row1 * DD + n) = v1;
            } else {
                const int part = n >> 10;
                const int hc = n & (DD - 1);
                const int h = hc >> 6;
                const int d = hc & 63;
                const int b0_ = row0 >> 11, s0_ = row0 & (SS - 1);
                const int b1_ = row1 >> 11, s1_ = row1 & (SS - 1);
                const size_t d0 = (((size_t)(b0_ * HH + h)) * SS + s0_) * HD + d;
                const size_t d1 = (((size_t)(b1_ * HH + h)) * SS + s1_) * HD + d;
                if (part == 0) {
                    *(__half2*)(g_qh + d0) = __floats2half2_rn(v0.x * QSCALE, v0.y * QSCALE);
                    *(__half2*)(g_qh + d1) = __floats2half2_rn(v1.x * QSCALE, v1.y * QSCALE);
                } else if (part == 1) {
                    *(float2*)(out1 + d0) = v0;       // exact -> present
                    *(float2*)(out1 + d1) = v1;
                    *(__half2*)(g_krh + d0) = __floats2half2_rn(v0.x, v0.y);
                    *(__half2*)(g_krh + d1) = __floats2half2_rn(v1.x, v1.y);
                } else {
                    *(float2*)(out2 + d0) = v0;
                    *(float2*)(out2 + d1) = v1;
                    *(__half2*)(g_vrh + d0) = __floats2half2_rn(v0.x, v0.y);
                    *(__half2*)(g_vrh + d1) = __floats2half2_rn(v1.x, v1.y);
                }
            }
        }
    }
}

// ---------------------------------------------------------------------------
// fp16 tensor-core causal flash attention, base-2 softmax with h2exp2.
// CTA: 256 threads (8 warps), 128 queries; key tiles of 64, 2 stages, 2 CTA/SM,
// heaviest q-blocks scheduled first. Scores are in log2 domain (q pre-scaled).
// ---------------------------------------------------------------------------
#define HKOFF(s) ((uint32_t)(s) * 9216u)
#define HVOFF(s) (18432u + (uint32_t)(s) * 9216u)
#define HPOFF 36864u
#define ATT_SMEM 55296

__global__ __launch_bounds__(256, 2) void attn_h(
    const __half* __restrict__ qh, const __half* __restrict__ kh,
    const __half* __restrict__ vh)
{
    extern __shared__ char smc[];
    const uint32_t sb = smem_u32(smc);
    const int tid = threadIdx.x;
    const int w = tid >> 5, lane = tid & 31;
    const int g = lane >> 2, tig = lane & 3;
    const int bh = blockIdx.x;
    const int qblk = (gridDim.y - 1) - blockIdx.y;   // heaviest blocks first
    const int q0 = qblk * 128;
    const int tmax = 2 * qblk + 1;
    const __half* kbase = kh + (size_t)bh * SS * HD;
    const __half* vbase = vh + (size_t)bh * SS * HD;

#define HISSUE(t) do {                                                             \
    const int _st = (t) & 1;                                                       \
    const int _k0 = (t) * 64;                                                      \
    _Pragma("unroll")                                                              \
    for (int _i = 0; _i < 2; _i++) {                                               \
        const int _f = tid + 256 * _i;                                             \
        const int _r = _f >> 3;                                                    \
        const int _c = (_f & 7) * 16;                                              \
        cp_async16(sb + HKOFF(_st) + (uint32_t)(_r * 144 + _c),                    \
                   (const char*)(kbase + (size_t)(_k0 + _r) * HD) + _c);           \
        cp_async16(sb + HVOFF(_st) + (uint32_t)(_r * 144 + _c),                    \
                   (const char*)(vbase + (size_t)(_k0 + _r) * HD) + _c);           \
    }                                                                              \
    CP_COMMIT();                                                                   \
} while (0)

    {
        const __half* qb = qh + ((size_t)bh * SS + q0) * HD;
#pragma unroll
        for (int i = 0; i < 4; i++) {
            const int f = tid + 256 * i;
            const int r = f >> 3;
            const int c = (f & 7) * 16;
            cp_async16(sb + HPOFF + (uint32_t)(r * 144 + c),
                       (const char*)(qb + (size_t)r * HD) + c);
        }
        CP_COMMIT();
    }
    HISSUE(0);
    CP_WAIT(1);
    __syncthreads();

    const int r0 = w * 16 + g;
    const uint32_t a_lane = (uint32_t)((w * 16 + ((lane >> 3) & 1) * 8 + (lane & 7)) * 144
                                       + ((lane >> 4) & 1) * 16);
    const uint32_t k_lane = (uint32_t)((((lane >> 4) & 1) * 8 + (lane & 7)) * 144
                                       + ((lane >> 3) & 1) * 16);
    const uint32_t v_lane = (uint32_t)((((lane >> 3) & 1) * 8 + (lane & 7)) * 144
                                       + ((lane >> 4) & 1) * 16);

    uint32_t qa[4][4];
#pragma unroll
    for (int kc = 0; kc < 4; kc++)
        LDSM_X4(qa[kc][0], qa[kc][1], qa[kc][2], qa[kc][3],
                sb + HPOFF + a_lane + kc * 32);
    __syncthreads();

    float o[8][4];
#pragma unroll
    for (int i = 0; i < 8; i++)
#pragma unroll
        for (int j = 0; j < 4; j++) o[i][j] = 0.f;
    float m0 = -1e30f, m1 = -1e30f, l0 = 0.f, l1 = 0.f;

    for (int t = 0; t <= tmax; t++) {
        const int st = t & 1;
        CP_WAIT(0);
        __syncthreads();
        if (t < tmax) HISSUE(t + 1);

        float s[8][4];
#pragma unroll
        for (int i = 0; i < 8; i++)
#pragma unroll
            for (int j = 0; j < 4; j++) s[i][j] = 0.f;

#pragma unroll
        for (int kc = 0; kc < 4; kc++) {
            uint32_t kb[8][2];
#pragma unroll
            for (int ntp = 0; ntp < 4; ntp++)
                LDSM_X4(kb[2 * ntp][0], kb[2 * ntp][1],
                        kb[2 * ntp + 1][0], kb[2 * ntp + 1][1],
                        sb + HKOFF(st) + k_lane + (uint32_t)(ntp * 16 * 144) + kc * 32);
#pragma unroll
            for (int nt = 0; nt < 8; nt++)
                mma_f16(s[nt], qa[kc], kb[nt]);
        }

        if (t >= 2 * qblk) {
            const int qg0 = q0 + r0;
            const int qg1 = qg0 + 8;
            const int kb0 = t * 64;
#pragma unroll
            for (int nt = 0; nt < 8; nt++) {
                const int col = kb0 + 8 * nt + 2 * tig;
                if (col > qg0)     s[nt][0] = -1e30f;
                if (col + 1 > qg0) s[nt][1] = -1e30f;
                if (col > qg1)     s[nt][2] = -1e30f;
                if (col + 1 > qg1) s[nt][3] = -1e30f;
            }
        }

        float mx0 = -1e30f, mx1 = -1e30f;
#pragma unroll
        for (int nt = 0; nt < 8; nt++) {
            mx0 = fmaxf(mx0, fmaxf(s[nt][0], s[nt][1]));
            mx1 = fmaxf(mx1, fmaxf(s[nt][2], s[nt][3]));
        }
        mx0 = fmaxf(mx0, __shfl_xor_sync(0xffffffffu, mx0, 1));
        mx0 = fmaxf(mx0, __shfl_xor_sync(0xffffffffu, mx0, 2));
        mx1 = fmaxf(mx1, __shfl_xor_sync(0xffffffffu, mx1, 1));
        mx1 = fmaxf(mx1, __shfl_xor_sync(0xffffffffu, mx1, 2));

        const float mn0 = fmaxf(m0, mx0);
        const float mn1 = fmaxf(m1, mx1);
        const float a0 = exp2f(m0 - mn0);
        const float a1 = exp2f(m1 - mn1);
        m0 = mn0; m1 = mn1;
        l0 *= a0; l1 *= a1;
#pragma unroll
        for (int nt = 0; nt < 8; nt++) {
            o[nt][0] *= a0; o[nt][1] *= a0;
            o[nt][2] *= a1; o[nt][3] *= a1;
        }

        // exp2 in packed fp16 (1 MUFU per 2 elements); P stored directly,
        // row sums accumulated from the SAME fp16 p values used in P@V.
        __half* Ps = (__half*)(smc + HPOFF);
        float rs0 = 0.f, rs1 = 0.f;
#pragma unroll
        for (int nt = 0; nt < 8; nt++) {
            __half2 hp0 = h2exp2(__floats2half2_rn(s[nt][0] - mn0, s[nt][1] - mn0));
            __half2 hp1 = h2exp2(__floats2half2_rn(s[nt][2] - mn1, s[nt][3] - mn1));
            *(__half2*)(Ps + r0 * 72 + 8 * nt + 2 * tig) = hp0;
            *(__half2*)(Ps + (r0 + 8) * 72 + 8 * nt + 2 * tig) = hp1;
            const float2 f0 = __half22float2(hp0);
            const float2 f1 = __half22float2(hp1);
            rs0 += f0.x + f0.y;
            rs1 += f1.x + f1.y;
        }
        rs0 += __shfl_xor_sync(0xffffffffu, rs0, 1);
        rs0 += __shfl_xor_sync(0xffffffffu, rs0, 2);
        rs1 += __shfl_xor_sync(0xffffffffu, rs1, 1);
        rs1 += __shfl_xor_sync(0xffffffffu, rs1, 2);
        l0 += rs0; l1 += rs1;

        __syncwarp();

#pragma unroll
        for (int kc = 0; kc < 4; kc++) {
            uint32_t pa[4];
            LDSM_X4(pa[0], pa[1], pa[2], pa[3], sb + HPOFF + a_lane + kc * 32);
            uint32_t vb[8][2];
#pragma unroll
            for (int ntp = 0; ntp < 4; ntp++)
                LDSM_X4_T(vb[2 * ntp][0], vb[2 * ntp][1],
                          vb[2 * ntp + 1][0], vb[2 * ntp + 1][1],
                          sb + HVOFF(st) + v_lane + (uint32_t)(kc * 16 * 144) + ntp * 32);
#pragma unroll
            for (int nt = 0; nt < 8; nt++)
                mma_f16(o[nt], pa, vb[nt]);
        }
    }

    const float inv0 = 1.0f / l0;
    const float inv1 = 1.0f / l1;
    const int b = bh >> 4, h = bh & 15;
    const size_t base0 = ((size_t)b * SS + q0 + r0) * DD + h * 64;
    const size_t base1 = ((size_t)b * SS + q0 + r0 + 8) * DD + h * 64;
#pragma unroll
    for (int nt = 0; nt < 8; nt++) {
        const int col = 8 * nt + 2 * tig;
        *(__half2*)(g_a + base0 + col) = __floats2half2_rn(o[nt][0] * inv0, o[nt][1] * inv0);
        *(__half2*)(g_a + base1 + col) = __floats2half2_rn(o[nt][2] * inv1, o[nt][3] * inv1);
    }
}

// ---------------------------------------------------------------------------
extern "C" void kernel_launch(void* const* d_in, const int* in_sizes, int n_in,
                              void* d_out, int out_size)
{
    const float* x      = (const float*)d_in[0];
    const float* w_attn = (const float*)d_in[1];
    const float* b_attn = (const float*)d_in[2];
    const float* w_proj = (const float*)d_in[3];
    const float* b_proj = (const float*)d_in[4];

    float* out  = (float*)d_out;
    float* kout = out + (size_t)BB * SS * DD;
    float* vout = kout + (size_t)BB * HH * SS * HD;

    __half *xh, *wah, *wth, *ah, *qh, *krh, *vrh;
    cudaGetSymbolAddress((void**)&xh, g_xh);
    cudaGetSymbolAddress((void**)&wah, g_wah);
    cudaGetSymbolAddress((void**)&wth, g_wth);
    cudaGetSymbolAddress((void**)&ah, g_a);
    cudaGetSymbolAddress((void**)&qh, g_qh);
    cudaGetSymbolAddress((void**)&krh, g_krh);
    cudaGetSymbolAddress((void**)&vrh, g_vrh);

    cudaFuncSetAttribute(mma_gemm_h<0>, cudaFuncAttributeMaxDynamicSharedMemorySize, GEMM_SMEM);
    cudaFuncSetAttribute(mma_gemm_h<1>, cudaFuncAttributeMaxDynamicSharedMemorySize, GEMM_SMEM);
    cudaFuncSetAttribute(attn_h, cudaFuncAttributeMaxDynamicSharedMemorySize, ATT_SMEM);

    // Fused prep: transpose+round w_proj, round x, round w_attn
    prep_kernel<<<1024, 256>>>((const float4*)x, (uint2*)xh, BB * SS * DD / 4,
                               (const float4*)w_attn, (uint2*)wah, 3 * DD * DD / 4,
                               w_proj, wth);

    // QKV GEMM (fp16): q*0.125*log2e->g_qh, k/v exact->present + fp16 copies
    mma_gemm_h<1><<<dim3(3 * DD / 128, BB * SS / 128), 256, GEMM_SMEM>>>(
        xh, wah, b_attn, nullptr, kout, vout);

    // fp16 flash attention (base-2 softmax) -> g_a
    attn_h<<<dim3(BB * HH, SS / 128), 256, ATT_SMEM>>>(qh, krh, vrh);

    // Proj GEMM (fp16) -> out
    mma_gemm_h<0><<<dim3(DD / 128, BB * SS / 128), 256, GEMM_SMEM>>>(
        ah, wth, b_proj, out, nullptr, nullptr);
}